// round 3
// baseline (speedup 1.0000x reference)
#include <cuda_runtime.h>
#include <math.h>

#define Dm   768
#define Hn   12
#define HS   64
#define Ln   12
#define Tt   1024
#define Bb   4
#define Vv   50257
#define MR   4096            // B*T rows
#define FF   3072
#define EPSL 1e-5f

// ---------------- scratch (static device globals; no runtime alloc) ----------
__device__ float g_x[MR * Dm];
__device__ float g_h[MR * Dm];
__device__ float g_q[MR * Dm];
__device__ float g_k[MR * Dm];
__device__ float g_v[MR * Dm];
__device__ float g_ao[MR * Dm];
__device__ float g_mlp[MR * FF];
__device__ float g_att[(size_t)Bb * Hn * Tt * Tt];   // 192 MB
__device__ float g_nll[MR];

// ---------------- embedding --------------------------------------------------
__global__ void embed_kernel(const int* __restrict__ idx,
                             const float* __restrict__ tok,
                             const float* __restrict__ pos,
                             float* __restrict__ x) {
    int row = blockIdx.x;                 // 0..4095
    int t = row & (Tt - 1);
    int tk = idx[row];
    const float* te = tok + (size_t)tk * Dm;
    const float* pe = pos + (size_t)t * Dm;
    float* xo = x + (size_t)row * Dm;
    for (int i = threadIdx.x; i < Dm; i += blockDim.x)
        xo[i] = te[i] + pe[i];
}

// ---------------- layernorm (one block of 256 per row, D=768=3*256) ----------
__global__ void ln_kernel(const float* __restrict__ x,
                          const float* __restrict__ gs,
                          const float* __restrict__ gb,
                          float* __restrict__ out) {
    int row = blockIdx.x;
    int tid = threadIdx.x;
    const float* xr = x + (size_t)row * Dm;
    float* orow = out + (size_t)row * Dm;

    float v0 = xr[tid], v1 = xr[tid + 256], v2 = xr[tid + 512];
    float s = v0 + v1 + v2;
    __shared__ float red[8];
    #pragma unroll
    for (int o = 16; o; o >>= 1) s += __shfl_xor_sync(0xffffffffu, s, o);
    if ((tid & 31) == 0) red[tid >> 5] = s;
    __syncthreads();
    float mean = (red[0]+red[1]+red[2]+red[3]+red[4]+red[5]+red[6]+red[7]) * (1.0f / Dm);
    __syncthreads();

    float d0 = v0 - mean, d1 = v1 - mean, d2 = v2 - mean;
    float sq = d0*d0 + d1*d1 + d2*d2;
    #pragma unroll
    for (int o = 16; o; o >>= 1) sq += __shfl_xor_sync(0xffffffffu, sq, o);
    if ((tid & 31) == 0) red[tid >> 5] = sq;
    __syncthreads();
    float var = (red[0]+red[1]+red[2]+red[3]+red[4]+red[5]+red[6]+red[7]) * (1.0f / Dm);
    float rs = rsqrtf(var + EPSL);

    orow[tid]       = d0 * rs * gs[tid]       + gb[tid];
    orow[tid + 256] = d1 * rs * gs[tid + 256] + gb[tid + 256];
    orow[tid + 512] = d2 * rs * gs[tid + 512] + gb[tid + 512];
}

// ---------------- generic SGEMM: C = A[MxK] @ B[KxN] (+bias)(+res)(relu) -----
// 64x64 tile, BK=16, 256 threads, 4x4 per thread. M%64==0, K%16==0 assumed.
__global__ void gemm64(const float* __restrict__ A, const float* __restrict__ Bm,
                       const float* __restrict__ bias, const float* __restrict__ res,
                       float* __restrict__ C, int M, int N, int K, int relu) {
    __shared__ float As[16][64];
    __shared__ float Bs[16][64];
    int tid = threadIdx.x;
    int tx = tid & 15, ty = tid >> 4;
    int m0 = blockIdx.y * 64, n0 = blockIdx.x * 64;

    int arow = tid >> 2;            // 0..63
    int acol = (tid & 3) * 4;       // 0,4,8,12
    int brow = tid >> 4;            // 0..15
    int bcol = (tid & 15) * 4;      // 0..60

    bool nfull = (n0 + 64 <= N);
    bool fast  = nfull && ((N & 3) == 0);   // B float4 path needs N%4==0

    const float* Ap = A + (size_t)(m0 + arow) * K + acol;
    float acc[4][4] = {};

    for (int k0 = 0; k0 < K; k0 += 16) {
        float4 av = *(const float4*)(Ap + k0);
        As[acol + 0][arow] = av.x;
        As[acol + 1][arow] = av.y;
        As[acol + 2][arow] = av.z;
        As[acol + 3][arow] = av.w;

        const float* Bp = Bm + (size_t)(k0 + brow) * N + n0 + bcol;
        if (fast) {
            float4 bv = *(const float4*)Bp;
            *(float4*)&Bs[brow][bcol] = bv;
        } else {
            #pragma unroll
            for (int j = 0; j < 4; j++)
                Bs[brow][bcol + j] = (n0 + bcol + j < N) ? Bp[j] : 0.0f;
        }
        __syncthreads();

        #pragma unroll
        for (int kk = 0; kk < 16; kk++) {
            float ra[4], rb[4];
            #pragma unroll
            for (int i = 0; i < 4; i++) ra[i] = As[kk][ty * 4 + i];
            #pragma unroll
            for (int j = 0; j < 4; j++) rb[j] = Bs[kk][tx * 4 + j];
            #pragma unroll
            for (int i = 0; i < 4; i++)
                #pragma unroll
                for (int j = 0; j < 4; j++)
                    acc[i][j] = fmaf(ra[i], rb[j], acc[i][j]);
        }
        __syncthreads();
    }

    #pragma unroll
    for (int i = 0; i < 4; i++) {
        int m = m0 + ty * 4 + i;
        #pragma unroll
        for (int j = 0; j < 4; j++) {
            int n = n0 + tx * 4 + j;
            if (n < N) {
                float v = acc[i][j];
                if (bias) v += bias[n];
                if (res)  v += res[(size_t)m * N + n];
                if (relu) v = fmaxf(v, 0.0f);
                C[(size_t)m * N + n] = v;
            }
        }
    }
}

// ---------------- attention scores: S = scale * Q K^T (causal tiles only) ----
// grid (s_tile=16, t_tile=16, bh=48), block 256
__global__ void attn_scores(const float* __restrict__ q, const float* __restrict__ k,
                            float* __restrict__ att) {
    int bh = blockIdx.z;
    int b = bh / Hn, h = bh % Hn;
    int t0 = blockIdx.y * 64, s0 = blockIdx.x * 64;
    if (s0 > t0) return;                      // fully non-causal tile

    __shared__ float Qs[16][64];
    __shared__ float Ks[16][64];
    int tid = threadIdx.x;
    int tx = tid & 15, ty = tid >> 4;
    int lrow = tid >> 2;                      // 0..63
    int lcol = (tid & 3) * 4;                 // 0,4,8,12

    const float* qp = q + (size_t)(b * Tt + t0 + lrow) * Dm + h * HS + lcol;
    const float* kp = k + (size_t)(b * Tt + s0 + lrow) * Dm + h * HS + lcol;
    float acc[4][4] = {};

    #pragma unroll
    for (int k0 = 0; k0 < HS; k0 += 16) {
        float4 qv = *(const float4*)(qp + k0);
        Qs[lcol + 0][lrow] = qv.x; Qs[lcol + 1][lrow] = qv.y;
        Qs[lcol + 2][lrow] = qv.z; Qs[lcol + 3][lrow] = qv.w;
        float4 kv = *(const float4*)(kp + k0);
        Ks[lcol + 0][lrow] = kv.x; Ks[lcol + 1][lrow] = kv.y;
        Ks[lcol + 2][lrow] = kv.z; Ks[lcol + 3][lrow] = kv.w;
        __syncthreads();
        #pragma unroll
        for (int kk = 0; kk < 16; kk++) {
            float ra[4], rb[4];
            #pragma unroll
            for (int i = 0; i < 4; i++) ra[i] = Qs[kk][ty * 4 + i];
            #pragma unroll
            for (int j = 0; j < 4; j++) rb[j] = Ks[kk][tx * 4 + j];
            #pragma unroll
            for (int i = 0; i < 4; i++)
                #pragma unroll
                for (int j = 0; j < 4; j++)
                    acc[i][j] = fmaf(ra[i], rb[j], acc[i][j]);
        }
        __syncthreads();
    }

    const float scale = 0.125f;   // 1/sqrt(64)
    #pragma unroll
    for (int i = 0; i < 4; i++) {
        int t = t0 + ty * 4 + i;
        float* arow = att + ((size_t)bh * Tt + t) * Tt;
        #pragma unroll
        for (int j = 0; j < 4; j++) {
            int s = s0 + tx * 4 + j;
            float v = acc[i][j] * scale;
            arow[s] = (s > t) ? -INFINITY : v;
        }
    }
}

// ---------------- causal softmax over att row (len = t+1), zero-pad to tile --
__global__ void softmax_kernel(float* __restrict__ att) {
    int t = blockIdx.x;
    int bh = blockIdx.y;
    float* row = att + ((size_t)bh * Tt + t) * Tt;
    int len = t + 1;
    int tile_end = ((t >> 6) + 1) << 6;
    int tid = threadIdx.x;

    __shared__ float red[4];
    __shared__ float bmax, bsum;

    float m = -INFINITY;
    for (int i = tid; i < len; i += 128) m = fmaxf(m, row[i]);
    #pragma unroll
    for (int o = 16; o; o >>= 1) m = fmaxf(m, __shfl_xor_sync(0xffffffffu, m, o));
    if ((tid & 31) == 0) red[tid >> 5] = m;
    __syncthreads();
    if (tid == 0) bmax = fmaxf(fmaxf(red[0], red[1]), fmaxf(red[2], red[3]));
    __syncthreads();
    m = bmax;

    float s = 0.0f;
    for (int i = tid; i < len; i += 128) s += expf(row[i] - m);
    #pragma unroll
    for (int o = 16; o; o >>= 1) s += __shfl_xor_sync(0xffffffffu, s, o);
    if ((tid & 31) == 0) red[tid >> 5] = s;
    __syncthreads();
    if (tid == 0) bsum = red[0] + red[1] + red[2] + red[3];
    __syncthreads();
    float inv = 1.0f / bsum;

    for (int i = tid; i < tile_end; i += 128)
        row[i] = (i < len) ? expf(row[i] - m) * inv : 0.0f;
}

// ---------------- O = att @ V  (per t-tile, only causal K extent) ------------
// grid (t_tile=16, bh=48), block 256
__global__ void attn_av(const float* __restrict__ att, const float* __restrict__ v,
                        float* __restrict__ ao) {
    int bh = blockIdx.y;
    int b = bh / Hn, h = bh % Hn;
    int t0 = blockIdx.x * 64;
    int kmax = t0 + 64;

    __shared__ float As[16][64];
    __shared__ float Bs[16][64];
    int tid = threadIdx.x;
    int tx = tid & 15, ty = tid >> 4;
    int arow = tid >> 2, acol = (tid & 3) * 4;
    int brow = tid >> 4, bcol = (tid & 15) * 4;

    const float* Ap = att + ((size_t)bh * Tt + t0 + arow) * Tt + acol;
    float acc[4][4] = {};

    for (int k0 = 0; k0 < kmax; k0 += 16) {
        float4 av = *(const float4*)(Ap + k0);
        As[acol + 0][arow] = av.x; As[acol + 1][arow] = av.y;
        As[acol + 2][arow] = av.z; As[acol + 3][arow] = av.w;
        float4 bv = *(const float4*)(v + (size_t)(b * Tt + k0 + brow) * Dm + h * HS + bcol);
        *(float4*)&Bs[brow][bcol] = bv;
        __syncthreads();
        #pragma unroll
        for (int kk = 0; kk < 16; kk++) {
            float ra[4], rb[4];
            #pragma unroll
            for (int i = 0; i < 4; i++) ra[i] = As[kk][ty * 4 + i];
            #pragma unroll
            for (int j = 0; j < 4; j++) rb[j] = Bs[kk][tx * 4 + j];
            #pragma unroll
            for (int i = 0; i < 4; i++)
                #pragma unroll
                for (int j = 0; j < 4; j++)
                    acc[i][j] = fmaf(ra[i], rb[j], acc[i][j]);
        }
        __syncthreads();
    }

    #pragma unroll
    for (int i = 0; i < 4; i++) {
        int t = t0 + ty * 4 + i;
        #pragma unroll
        for (int j = 0; j < 4; j++)
            ao[(size_t)(b * Tt + t) * Dm + h * HS + tx * 4 + j] = acc[i][j];
    }
}

// ---------------- per-row NLL via single-pass online logsumexp ---------------
__global__ void nll_kernel(const float* __restrict__ logits, const int* __restrict__ tgt,
                           float* __restrict__ nll) {
    int row = blockIdx.x;
    int tid = threadIdx.x;
    const float* lr = logits + (size_t)row * Vv;

    float m = -INFINITY, s = 0.0f;
    for (int i = tid; i < Vv; i += 256) {
        float x = lr[i];
        if (x > m) { s = s * expf(m - x) + 1.0f; m = x; }
        else       { s += expf(x - m); }
    }
    __shared__ float sm[256], ss[256];
    sm[tid] = m; ss[tid] = s;
    __syncthreads();
    for (int off = 128; off; off >>= 1) {
        if (tid < off) {
            float m2 = sm[tid + off], s2 = ss[tid + off];
            float mm = fmaxf(sm[tid], m2);
            ss[tid] = ss[tid] * expf(sm[tid] - mm) + s2 * expf(m2 - mm);
            sm[tid] = mm;
        }
        __syncthreads();
    }
    if (tid == 0) {
        float lse = sm[0] + logf(ss[0]);
        nll[row] = lse - lr[tgt[row]];
    }
}

__global__ void loss_reduce(const float* __restrict__ nll, float* __restrict__ out) {
    int tid = threadIdx.x;
    float s = 0.0f;
    for (int i = tid; i < MR; i += 256) s += nll[i];
    __shared__ float red[8];
    #pragma unroll
    for (int o = 16; o; o >>= 1) s += __shfl_xor_sync(0xffffffffu, s, o);
    if ((tid & 31) == 0) red[tid >> 5] = s;
    __syncthreads();
    if (tid == 0) {
        float tot = red[0]+red[1]+red[2]+red[3]+red[4]+red[5]+red[6]+red[7];
        out[0] = tot * (1.0f / MR);
    }
}

// ---------------- driver -----------------------------------------------------
extern "C" void kernel_launch(void* const* d_in, const int* in_sizes, int n_in,
                              void* d_out, int out_size) {
    const int*   idx   = (const int*)  d_in[0];
    const int*   tgt   = (const int*)  d_in[1];
    const float* tok   = (const float*)d_in[2];
    const float* pos   = (const float*)d_in[3];
    const float* ln1s  = (const float*)d_in[4];
    const float* ln1b  = (const float*)d_in[5];
    const float* Wq    = (const float*)d_in[6];
    const float* Wk    = (const float*)d_in[7];
    const float* Wv    = (const float*)d_in[8];
    const float* Wo    = (const float*)d_in[9];
    const float* bo    = (const float*)d_in[10];
    const float* ln2s  = (const float*)d_in[11];
    const float* ln2b  = (const float*)d_in[12];
    const float* W1    = (const float*)d_in[13];
    const float* b1    = (const float*)d_in[14];
    const float* W2    = (const float*)d_in[15];
    const float* b2    = (const float*)d_in[16];
    const float* lnfs  = (const float*)d_in[17];
    const float* lnfb  = (const float*)d_in[18];
    const float* lmW   = (const float*)d_in[19];
    const float* lmb   = (const float*)d_in[20];
    float* out = (float*)d_out;

    float *gx, *gh, *gq, *gk, *gv, *gao, *gmlp, *gatt, *gnll;
    cudaGetSymbolAddress((void**)&gx,   g_x);
    cudaGetSymbolAddress((void**)&gh,   g_h);
    cudaGetSymbolAddress((void**)&gq,   g_q);
    cudaGetSymbolAddress((void**)&gk,   g_k);
    cudaGetSymbolAddress((void**)&gv,   g_v);
    cudaGetSymbolAddress((void**)&gao,  g_ao);
    cudaGetSymbolAddress((void**)&gmlp, g_mlp);
    cudaGetSymbolAddress((void**)&gatt, g_att);
    cudaGetSymbolAddress((void**)&gnll, g_nll);

    embed_kernel<<<MR, 256>>>(idx, tok, pos, gx);

    dim3 gDD((Dm + 63) / 64, MR / 64);      // 12 x 64
    dim3 gFF((FF + 63) / 64, MR / 64);      // 48 x 64
    dim3 gSc(16, 16, Bb * Hn);
    dim3 gSm(Tt, Bb * Hn);
    dim3 gAv(16, Bb * Hn);

    for (int l = 0; l < Ln; l++) {
        const float* wq = Wq + (size_t)l * Dm * Dm;
        const float* wk = Wk + (size_t)l * Dm * Dm;
        const float* wv = Wv + (size_t)l * Dm * Dm;
        const float* wo = Wo + (size_t)l * Dm * Dm;
        const float* w1 = W1 + (size_t)l * Dm * FF;
        const float* w2 = W2 + (size_t)l * FF * Dm;

        ln_kernel<<<MR, 256>>>(gx, ln1s + l * Dm, ln1b + l * Dm, gh);
        gemm64<<<gDD, 256>>>(gh, wq, nullptr, nullptr, gq, MR, Dm, Dm, 0);
        gemm64<<<gDD, 256>>>(gh, wk, nullptr, nullptr, gk, MR, Dm, Dm, 0);
        gemm64<<<gDD, 256>>>(gh, wv, nullptr, nullptr, gv, MR, Dm, Dm, 0);

        attn_scores<<<gSc, 256>>>(gq, gk, gatt);
        softmax_kernel<<<gSm, 128>>>(gatt);
        attn_av<<<gAv, 256>>>(gatt, gv, gao);

        gemm64<<<gDD, 256>>>(gao, wo, bo + l * Dm, gx, gx, MR, Dm, Dm, 0);

        ln_kernel<<<MR, 256>>>(gx, ln2s + l * Dm, ln2b + l * Dm, gh);
        gemm64<<<gFF, 256>>>(gh, w1, b1 + (size_t)l * FF, nullptr, gmlp, MR, FF, Dm, 1);
        gemm64<<<gDD, 256>>>(gmlp, w2, b2 + l * Dm, gx, gx, MR, Dm, FF, 0);
    }

    ln_kernel<<<MR, 256>>>(gx, lnfs, lnfb, gh);
    dim3 gV((Vv + 63) / 64, MR / 64);       // 786 x 64
    gemm64<<<gV, 256>>>(gh, lmW, lmb, nullptr, out, MR, Vv, Dm, 0);

    nll_kernel<<<MR, 256>>>(out, tgt, gnll);
    loss_reduce<<<1, 256>>>(gnll, out + (size_t)out_size - 1);
}

// round 4
// speedup vs baseline: 1.9938x; 1.9938x over previous
#include <cuda_runtime.h>
#include <math.h>

#define Dm   768
#define Hn   12
#define HS   64
#define Ln   12
#define Tt   1024
#define Bb   4
#define Vv   50257
#define MR   4096            // B*T rows
#define FF   3072
#define EPSL 1e-5f

#define BM 128
#define BN 128
#define BK 16

// ---------------- scratch (static device globals; no runtime alloc) ----------
__device__ float g_x[MR * Dm];
__device__ float g_h[MR * Dm];
__device__ float g_q[MR * Dm];
__device__ float g_k[MR * Dm];
__device__ float g_v[MR * Dm];
__device__ float g_ao[MR * Dm];
__device__ float g_mlp[MR * FF];
__device__ float g_att[(size_t)Bb * Hn * Tt * Tt];   // 192 MB
__device__ float g_nll[MR];

// ---------------- embedding --------------------------------------------------
__global__ void embed_kernel(const int* __restrict__ idx,
                             const float* __restrict__ tok,
                             const float* __restrict__ pos,
                             float* __restrict__ x) {
    int row = blockIdx.x;
    int t = row & (Tt - 1);
    int tk = idx[row];
    const float* te = tok + (size_t)tk * Dm;
    const float* pe = pos + (size_t)t * Dm;
    float* xo = x + (size_t)row * Dm;
    for (int i = threadIdx.x; i < Dm; i += blockDim.x)
        xo[i] = te[i] + pe[i];
}

// ---------------- layernorm --------------------------------------------------
__global__ void ln_kernel(const float* __restrict__ x,
                          const float* __restrict__ gs,
                          const float* __restrict__ gb,
                          float* __restrict__ out) {
    int row = blockIdx.x;
    int tid = threadIdx.x;
    const float* xr = x + (size_t)row * Dm;
    float* orow = out + (size_t)row * Dm;

    float v0 = xr[tid], v1 = xr[tid + 256], v2 = xr[tid + 512];
    float s = v0 + v1 + v2;
    __shared__ float red[8];
    #pragma unroll
    for (int o = 16; o; o >>= 1) s += __shfl_xor_sync(0xffffffffu, s, o);
    if ((tid & 31) == 0) red[tid >> 5] = s;
    __syncthreads();
    float mean = (red[0]+red[1]+red[2]+red[3]+red[4]+red[5]+red[6]+red[7]) * (1.0f / Dm);
    __syncthreads();

    float d0 = v0 - mean, d1 = v1 - mean, d2 = v2 - mean;
    float sq = d0*d0 + d1*d1 + d2*d2;
    #pragma unroll
    for (int o = 16; o; o >>= 1) sq += __shfl_xor_sync(0xffffffffu, sq, o);
    if ((tid & 31) == 0) red[tid >> 5] = sq;
    __syncthreads();
    float var = (red[0]+red[1]+red[2]+red[3]+red[4]+red[5]+red[6]+red[7]) * (1.0f / Dm);
    float rs = rsqrtf(var + EPSL);

    orow[tid]       = d0 * rs * gs[tid]       + gb[tid];
    orow[tid + 256] = d1 * rs * gs[tid + 256] + gb[tid + 256];
    orow[tid + 512] = d2 * rs * gs[tid + 512] + gb[tid + 512];
}

// ---------------- tf32 tensor-core GEMM --------------------------------------
__device__ __forceinline__ unsigned f2tf(float f) {
    unsigned r;
    asm("cvt.rna.tf32.f32 %0, %1;" : "=r"(r) : "f"(f));
    return r;
}

__device__ __forceinline__ void mma_tf32(float* c, unsigned a0, unsigned a1,
                                         unsigned a2, unsigned a3,
                                         unsigned b0, unsigned b1) {
    asm volatile(
        "mma.sync.aligned.m16n8k8.row.col.f32.tf32.tf32.f32 "
        "{%0,%1,%2,%3}, {%4,%5,%6,%7}, {%8,%9}, {%0,%1,%2,%3};"
        : "+f"(c[0]), "+f"(c[1]), "+f"(c[2]), "+f"(c[3])
        : "r"(a0), "r"(a1), "r"(a2), "r"(a3), "r"(b0), "r"(b1));
}

// C = A[MxK] @ B[KxN] (+bias)(+res)(relu). M%128==0, K%16==0. N arbitrary.
// blockIdx.z selects (B,C) among up to 3 weight/output pairs (QKV fusion).
__global__ __launch_bounds__(256)
void gemm_tc(const float* __restrict__ A, const float* __restrict__ B,
             const float* __restrict__ bias, const float* __restrict__ res,
             float* __restrict__ C, int M, int N, int K, int relu,
             const float* B1, const float* B2, float* C1, float* C2) {
    if (blockIdx.z == 1) { B = B1; C = C1; }
    else if (blockIdx.z == 2) { B = B2; C = C2; }

    __shared__ unsigned As[2][BK][BM + 4];
    __shared__ unsigned Bs[2][BK][BN + 4];

    int tid = threadIdx.x;
    int lane = tid & 31, wid = tid >> 5;
    int g = lane >> 2, tig = lane & 3;
    int wm = wid & 1, wn = wid >> 1;        // 2 x 4 warp grid, warp tile 64x32

    int m0 = blockIdx.x * BM, n0 = blockIdx.y * BN;

    int arow = tid >> 1, acol = (tid & 1) * 8;    // A: 128 rows x 16 cols
    int brow = tid >> 4, bcol = (tid & 15) * 8;   // B: 16 rows x 128 cols

    bool fastB = (n0 + BN <= N) && ((N & 3) == 0);

    const float* Aptr = A + (size_t)(m0 + arow) * K + acol;

    float c[4][4][4] = {};

    // prologue: tile 0 -> buf 0
    {
        float va[8], vb[8];
        *(float4*)&va[0] = *(const float4*)(Aptr);
        *(float4*)&va[4] = *(const float4*)(Aptr + 4);
        const float* Bp = B + (size_t)brow * N + n0 + bcol;
        if (fastB) {
            *(float4*)&vb[0] = *(const float4*)Bp;
            *(float4*)&vb[4] = *(const float4*)(Bp + 4);
        } else {
            #pragma unroll
            for (int j = 0; j < 8; j++)
                vb[j] = (n0 + bcol + j < N) ? Bp[j] : 0.0f;
        }
        #pragma unroll
        for (int j = 0; j < 8; j++) As[0][acol + j][arow] = f2tf(va[j]);
        #pragma unroll
        for (int j = 0; j < 8; j++) Bs[0][brow][bcol + j] = f2tf(vb[j]);
    }
    __syncthreads();

    int nk = K / BK;
    for (int it = 0; it < nk; it++) {
        int buf = it & 1;
        float va[8], vb[8];
        bool more = (it + 1 < nk);
        if (more) {
            int k0 = (it + 1) * BK;
            *(float4*)&va[0] = *(const float4*)(Aptr + k0);
            *(float4*)&va[4] = *(const float4*)(Aptr + k0 + 4);
            const float* Bp = B + (size_t)(k0 + brow) * N + n0 + bcol;
            if (fastB) {
                *(float4*)&vb[0] = *(const float4*)Bp;
                *(float4*)&vb[4] = *(const float4*)(Bp + 4);
            } else {
                #pragma unroll
                for (int j = 0; j < 8; j++)
                    vb[j] = (n0 + bcol + j < N) ? Bp[j] : 0.0f;
            }
        }

        #pragma unroll
        for (int ks = 0; ks < BK; ks += 8) {
            unsigned af[4][4], bf[4][2];
            #pragma unroll
            for (int mi = 0; mi < 4; mi++) {
                int m = wm * 64 + mi * 16 + g;
                af[mi][0] = As[buf][ks + tig][m];
                af[mi][1] = As[buf][ks + tig][m + 8];
                af[mi][2] = As[buf][ks + tig + 4][m];
                af[mi][3] = As[buf][ks + tig + 4][m + 8];
            }
            #pragma unroll
            for (int ni = 0; ni < 4; ni++) {
                int n = wn * 32 + ni * 8 + g;
                bf[ni][0] = Bs[buf][ks + tig][n];
                bf[ni][1] = Bs[buf][ks + tig + 4][n];
            }
            #pragma unroll
            for (int mi = 0; mi < 4; mi++)
                #pragma unroll
                for (int ni = 0; ni < 4; ni++)
                    mma_tf32(c[mi][ni], af[mi][0], af[mi][1], af[mi][2], af[mi][3],
                             bf[ni][0], bf[ni][1]);
        }

        if (more) {
            int nb = buf ^ 1;
            #pragma unroll
            for (int j = 0; j < 8; j++) As[nb][acol + j][arow] = f2tf(va[j]);
            #pragma unroll
            for (int j = 0; j < 8; j++) Bs[nb][brow][bcol + j] = f2tf(vb[j]);
        }
        __syncthreads();
    }

    // epilogue
    #pragma unroll
    for (int mi = 0; mi < 4; mi++) {
        int r0 = m0 + wm * 64 + mi * 16 + g;
        #pragma unroll
        for (int ni = 0; ni < 4; ni++) {
            int col = n0 + wn * 32 + ni * 8 + 2 * tig;
            #pragma unroll
            for (int rr = 0; rr < 2; rr++) {
                int r = r0 + rr * 8;
                #pragma unroll
                for (int cc = 0; cc < 2; cc++) {
                    int nn = col + cc;
                    if (nn < N) {
                        float v = c[mi][ni][rr * 2 + cc];
                        if (bias) v += bias[nn];
                        if (res)  v += res[(size_t)r * N + nn];
                        if (relu) v = fmaxf(v, 0.0f);
                        C[(size_t)r * N + nn] = v;
                    }
                }
            }
        }
    }
}

// ---------------- attention scores (SIMT, causal tiles only) -----------------
__global__ void attn_scores(const float* __restrict__ q, const float* __restrict__ k,
                            float* __restrict__ att) {
    int bh = blockIdx.z;
    int b = bh / Hn, h = bh % Hn;
    int t0 = blockIdx.y * 64, s0 = blockIdx.x * 64;
    if (s0 > t0) return;

    __shared__ float Qs[16][64];
    __shared__ float Ks[16][64];
    int tid = threadIdx.x;
    int tx = tid & 15, ty = tid >> 4;
    int lrow = tid >> 2;
    int lcol = (tid & 3) * 4;

    const float* qp = q + (size_t)(b * Tt + t0 + lrow) * Dm + h * HS + lcol;
    const float* kp = k + (size_t)(b * Tt + s0 + lrow) * Dm + h * HS + lcol;
    float acc[4][4] = {};

    #pragma unroll
    for (int k0 = 0; k0 < HS; k0 += 16) {
        float4 qv = *(const float4*)(qp + k0);
        Qs[lcol + 0][lrow] = qv.x; Qs[lcol + 1][lrow] = qv.y;
        Qs[lcol + 2][lrow] = qv.z; Qs[lcol + 3][lrow] = qv.w;
        float4 kv = *(const float4*)(kp + k0);
        Ks[lcol + 0][lrow] = kv.x; Ks[lcol + 1][lrow] = kv.y;
        Ks[lcol + 2][lrow] = kv.z; Ks[lcol + 3][lrow] = kv.w;
        __syncthreads();
        #pragma unroll
        for (int kk = 0; kk < 16; kk++) {
            float ra[4], rb[4];
            #pragma unroll
            for (int i = 0; i < 4; i++) ra[i] = Qs[kk][ty * 4 + i];
            #pragma unroll
            for (int j = 0; j < 4; j++) rb[j] = Ks[kk][tx * 4 + j];
            #pragma unroll
            for (int i = 0; i < 4; i++)
                #pragma unroll
                for (int j = 0; j < 4; j++)
                    acc[i][j] = fmaf(ra[i], rb[j], acc[i][j]);
        }
        __syncthreads();
    }

    const float scale = 0.125f;
    #pragma unroll
    for (int i = 0; i < 4; i++) {
        int t = t0 + ty * 4 + i;
        float* arow = att + ((size_t)bh * Tt + t) * Tt;
        #pragma unroll
        for (int j = 0; j < 4; j++) {
            int s = s0 + tx * 4 + j;
            float v = acc[i][j] * scale;
            arow[s] = (s > t) ? -INFINITY : v;
        }
    }
}

// ---------------- causal softmax ---------------------------------------------
__global__ void softmax_kernel(float* __restrict__ att) {
    int t = blockIdx.x;
    int bh = blockIdx.y;
    float* row = att + ((size_t)bh * Tt + t) * Tt;
    int len = t + 1;
    int tile_end = ((t >> 6) + 1) << 6;
    int tid = threadIdx.x;

    __shared__ float red[4];
    __shared__ float bmax, bsum;

    float m = -INFINITY;
    for (int i = tid; i < len; i += 128) m = fmaxf(m, row[i]);
    #pragma unroll
    for (int o = 16; o; o >>= 1) m = fmaxf(m, __shfl_xor_sync(0xffffffffu, m, o));
    if ((tid & 31) == 0) red[tid >> 5] = m;
    __syncthreads();
    if (tid == 0) bmax = fmaxf(fmaxf(red[0], red[1]), fmaxf(red[2], red[3]));
    __syncthreads();
    m = bmax;

    float s = 0.0f;
    for (int i = tid; i < len; i += 128) s += expf(row[i] - m);
    #pragma unroll
    for (int o = 16; o; o >>= 1) s += __shfl_xor_sync(0xffffffffu, s, o);
    if ((tid & 31) == 0) red[tid >> 5] = s;
    __syncthreads();
    if (tid == 0) bsum = red[0] + red[1] + red[2] + red[3];
    __syncthreads();
    float inv = 1.0f / bsum;

    for (int i = tid; i < tile_end; i += 128)
        row[i] = (i < len) ? expf(row[i] - m) * inv : 0.0f;
}

// ---------------- O = att @ V ------------------------------------------------
__global__ void attn_av(const float* __restrict__ att, const float* __restrict__ v,
                        float* __restrict__ ao) {
    int bh = blockIdx.y;
    int b = bh / Hn, h = bh % Hn;
    int t0 = blockIdx.x * 64;
    int kmax = t0 + 64;

    __shared__ float As[16][64];
    __shared__ float Bs[16][64];
    int tid = threadIdx.x;
    int tx = tid & 15, ty = tid >> 4;
    int arow = tid >> 2, acol = (tid & 3) * 4;
    int brow = tid >> 4, bcol = (tid & 15) * 4;

    const float* Ap = att + ((size_t)bh * Tt + t0 + arow) * Tt + acol;
    float acc[4][4] = {};

    for (int k0 = 0; k0 < kmax; k0 += 16) {
        float4 av = *(const float4*)(Ap + k0);
        As[acol + 0][arow] = av.x; As[acol + 1][arow] = av.y;
        As[acol + 2][arow] = av.z; As[acol + 3][arow] = av.w;
        float4 bv = *(const float4*)(v + (size_t)(b * Tt + k0 + brow) * Dm + h * HS + bcol);
        *(float4*)&Bs[brow][bcol] = bv;
        __syncthreads();
        #pragma unroll
        for (int kk = 0; kk < 16; kk++) {
            float ra[4], rb[4];
            #pragma unroll
            for (int i = 0; i < 4; i++) ra[i] = As[kk][ty * 4 + i];
            #pragma unroll
            for (int j = 0; j < 4; j++) rb[j] = Bs[kk][tx * 4 + j];
            #pragma unroll
            for (int i = 0; i < 4; i++)
                #pragma unroll
                for (int j = 0; j < 4; j++)
                    acc[i][j] = fmaf(ra[i], rb[j], acc[i][j]);
        }
        __syncthreads();
    }

    #pragma unroll
    for (int i = 0; i < 4; i++) {
        int t = t0 + ty * 4 + i;
        #pragma unroll
        for (int j = 0; j < 4; j++)
            ao[(size_t)(b * Tt + t) * Dm + h * HS + tx * 4 + j] = acc[i][j];
    }
}

// ---------------- per-row NLL ------------------------------------------------
__global__ void nll_kernel(const float* __restrict__ logits, const int* __restrict__ tgt,
                           float* __restrict__ nll) {
    int row = blockIdx.x;
    int tid = threadIdx.x;
    const float* lr = logits + (size_t)row * Vv;

    float m = -INFINITY, s = 0.0f;
    for (int i = tid; i < Vv; i += 256) {
        float x = lr[i];
        if (x > m) { s = s * expf(m - x) + 1.0f; m = x; }
        else       { s += expf(x - m); }
    }
    __shared__ float sm[256], ss[256];
    sm[tid] = m; ss[tid] = s;
    __syncthreads();
    for (int off = 128; off; off >>= 1) {
        if (tid < off) {
            float m2 = sm[tid + off], s2 = ss[tid + off];
            float mm = fmaxf(sm[tid], m2);
            ss[tid] = ss[tid] * expf(sm[tid] - mm) + s2 * expf(m2 - mm);
            sm[tid] = mm;
        }
        __syncthreads();
    }
    if (tid == 0) {
        float lse = sm[0] + logf(ss[0]);
        nll[row] = lse - lr[tgt[row]];
    }
}

__global__ void loss_reduce(const float* __restrict__ nll, float* __restrict__ out) {
    int tid = threadIdx.x;
    float s = 0.0f;
    for (int i = tid; i < MR; i += 256) s += nll[i];
    __shared__ float red[8];
    #pragma unroll
    for (int o = 16; o; o >>= 1) s += __shfl_xor_sync(0xffffffffu, s, o);
    if ((tid & 31) == 0) red[tid >> 5] = s;
    __syncthreads();
    if (tid == 0) {
        float tot = red[0]+red[1]+red[2]+red[3]+red[4]+red[5]+red[6]+red[7];
        out[0] = tot * (1.0f / MR);
    }
}

// ---------------- driver -----------------------------------------------------
extern "C" void kernel_launch(void* const* d_in, const int* in_sizes, int n_in,
                              void* d_out, int out_size) {
    const int*   idx   = (const int*)  d_in[0];
    const int*   tgt   = (const int*)  d_in[1];
    const float* tok   = (const float*)d_in[2];
    const float* pos   = (const float*)d_in[3];
    const float* ln1s  = (const float*)d_in[4];
    const float* ln1b  = (const float*)d_in[5];
    const float* Wq    = (const float*)d_in[6];
    const float* Wk    = (const float*)d_in[7];
    const float* Wv    = (const float*)d_in[8];
    const float* Wo    = (const float*)d_in[9];
    const float* bo    = (const float*)d_in[10];
    const float* ln2s  = (const float*)d_in[11];
    const float* ln2b  = (const float*)d_in[12];
    const float* W1    = (const float*)d_in[13];
    const float* b1    = (const float*)d_in[14];
    const float* W2    = (const float*)d_in[15];
    const float* b2    = (const float*)d_in[16];
    const float* lnfs  = (const float*)d_in[17];
    const float* lnfb  = (const float*)d_in[18];
    const float* lmW   = (const float*)d_in[19];
    const float* lmb   = (const float*)d_in[20];
    float* out = (float*)d_out;

    float *gx, *gh, *gq, *gk, *gv, *gao, *gmlp, *gatt, *gnll;
    cudaGetSymbolAddress((void**)&gx,   g_x);
    cudaGetSymbolAddress((void**)&gh,   g_h);
    cudaGetSymbolAddress((void**)&gq,   g_q);
    cudaGetSymbolAddress((void**)&gk,   g_k);
    cudaGetSymbolAddress((void**)&gv,   g_v);
    cudaGetSymbolAddress((void**)&gao,  g_ao);
    cudaGetSymbolAddress((void**)&gmlp, g_mlp);
    cudaGetSymbolAddress((void**)&gatt, g_att);
    cudaGetSymbolAddress((void**)&gnll, g_nll);

    embed_kernel<<<MR, 256>>>(idx, tok, pos, gx);

    dim3 gQKV(MR / BM, Dm / BN, 3);          // 32 x 6 x 3
    dim3 gDD (MR / BM, Dm / BN, 1);          // 32 x 6
    dim3 gF1 (MR / BM, FF / BN, 1);          // 32 x 24
    dim3 gSc(16, 16, Bb * Hn);
    dim3 gSm(Tt, Bb * Hn);
    dim3 gAv(16, Bb * Hn);

    for (int l = 0; l < Ln; l++) {
        const float* wq = Wq + (size_t)l * Dm * Dm;
        const float* wk = Wk + (size_t)l * Dm * Dm;
        const float* wv = Wv + (size_t)l * Dm * Dm;
        const float* wo = Wo + (size_t)l * Dm * Dm;
        const float* w1 = W1 + (size_t)l * Dm * FF;
        const float* w2 = W2 + (size_t)l * FF * Dm;

        ln_kernel<<<MR, 256>>>(gx, ln1s + l * Dm, ln1b + l * Dm, gh);
        gemm_tc<<<gQKV, 256>>>(gh, wq, nullptr, nullptr, gq, MR, Dm, Dm, 0,
                               wk, wv, gk, gv);

        attn_scores<<<gSc, 256>>>(gq, gk, gatt);
        softmax_kernel<<<gSm, 128>>>(gatt);
        attn_av<<<gAv, 256>>>(gatt, gv, gao);

        gemm_tc<<<gDD, 256>>>(gao, wo, bo + l * Dm, gx, gx, MR, Dm, Dm, 0,
                              nullptr, nullptr, nullptr, nullptr);

        ln_kernel<<<MR, 256>>>(gx, ln2s + l * Dm, ln2b + l * Dm, gh);
        gemm_tc<<<gF1, 256>>>(gh, w1, b1 + (size_t)l * FF, nullptr, gmlp,
                              MR, FF, Dm, 1, nullptr, nullptr, nullptr, nullptr);
        gemm_tc<<<gDD, 256>>>(gmlp, w2, b2 + l * Dm, gx, gx, MR, Dm, FF, 0,
                              nullptr, nullptr, nullptr, nullptr);
    }

    ln_kernel<<<MR, 256>>>(gx, lnfs, lnfb, gh);
    dim3 gV(MR / BM, (Vv + BN - 1) / BN, 1);   // 32 x 393
    gemm_tc<<<gV, 256>>>(gh, lmW, lmb, nullptr, out, MR, Vv, Dm, 0,
                         nullptr, nullptr, nullptr, nullptr);

    nll_kernel<<<MR, 256>>>(out, tgt, gnll);
    loss_reduce<<<1, 256>>>(gnll, out + (size_t)out_size - 1);
}

// round 9
// speedup vs baseline: 2.0814x; 1.0439x over previous
#include <cuda_runtime.h>
#include <math.h>

#define Dm   768
#define Hn   12
#define HS   64
#define Ln   12
#define Tt   1024
#define Bb   4
#define Vv   50257
#define NP   50304           // lm_W padded stride (multiple of 128)
#define MR   4096            // B*T rows
#define FF   3072
#define EPSL 1e-5f

#define BM 128
#define BN 128
#define BK 16

#define FA_PAD 68

// ---------------- scratch (static device globals; no runtime alloc) ----------
__device__ float g_x[MR * Dm];
__device__ float g_h[MR * Dm];
__device__ float g_q[MR * Dm];
__device__ float g_k[MR * Dm];
__device__ float g_v[MR * Dm];
__device__ float g_ao[MR * Dm];
__device__ float g_mlp[MR * FF];
__device__ float g_lmWp[(size_t)Dm * NP];    // padded lm_W, ~154 MB
__device__ float g_nll[MR];

// ---------------- embedding --------------------------------------------------
__global__ void embed_kernel(const int* __restrict__ idx,
                             const float* __restrict__ tok,
                             const float* __restrict__ pos,
                             float* __restrict__ x) {
    int row = blockIdx.x;
    int t = row & (Tt - 1);
    int tk = idx[row];
    const float* te = tok + (size_t)tk * Dm;
    const float* pe = pos + (size_t)t * Dm;
    float* xo = x + (size_t)row * Dm;
    for (int i = threadIdx.x; i < Dm; i += blockDim.x)
        xo[i] = te[i] + pe[i];
}

// ---------------- pad lm_W into stride-NP buffer ------------------------------
__global__ void pad_lmW(const float* __restrict__ w, float* __restrict__ wp) {
    int k = blockIdx.x;                                  // 0..767
    const float* src = w + (size_t)k * Vv;
    float* dst = wp + (size_t)k * NP;
    for (int j = threadIdx.x; j < NP; j += blockDim.x)
        dst[j] = (j < Vv) ? src[j] : 0.0f;
}

// ---------------- layernorm --------------------------------------------------
__global__ void ln_kernel(const float* __restrict__ x,
                          const float* __restrict__ gs,
                          const float* __restrict__ gb,
                          float* __restrict__ out) {
    int row = blockIdx.x;
    int tid = threadIdx.x;
    const float* xr = x + (size_t)row * Dm;
    float* orow = out + (size_t)row * Dm;

    float v0 = xr[tid], v1 = xr[tid + 256], v2 = xr[tid + 512];
    float s = v0 + v1 + v2;
    __shared__ float red[8];
    #pragma unroll
    for (int o = 16; o; o >>= 1) s += __shfl_xor_sync(0xffffffffu, s, o);
    if ((tid & 31) == 0) red[tid >> 5] = s;
    __syncthreads();
    float mean = (red[0]+red[1]+red[2]+red[3]+red[4]+red[5]+red[6]+red[7]) * (1.0f / Dm);
    __syncthreads();

    float d0 = v0 - mean, d1 = v1 - mean, d2 = v2 - mean;
    float sq = d0*d0 + d1*d1 + d2*d2;
    #pragma unroll
    for (int o = 16; o; o >>= 1) sq += __shfl_xor_sync(0xffffffffu, sq, o);
    if ((tid & 31) == 0) red[tid >> 5] = sq;
    __syncthreads();
    float var = (red[0]+red[1]+red[2]+red[3]+red[4]+red[5]+red[6]+red[7]) * (1.0f / Dm);
    float rs = rsqrtf(var + EPSL);

    orow[tid]       = d0 * rs * gs[tid]       + gb[tid];
    orow[tid + 256] = d1 * rs * gs[tid + 256] + gb[tid + 256];
    orow[tid + 512] = d2 * rs * gs[tid + 512] + gb[tid + 512];
}

// ---------------- tf32 tensor-core GEMM --------------------------------------
__device__ __forceinline__ unsigned f2tf(float f) {
    unsigned r;
    asm("cvt.rna.tf32.f32 %0, %1;" : "=r"(r) : "f"(f));
    return r;
}

__device__ __forceinline__ void mma_tf32(float* c, unsigned a0, unsigned a1,
                                         unsigned a2, unsigned a3,
                                         unsigned b0, unsigned b1) {
    asm volatile(
        "mma.sync.aligned.m16n8k8.row.col.f32.tf32.tf32.f32 "
        "{%0,%1,%2,%3}, {%4,%5,%6,%7}, {%8,%9}, {%0,%1,%2,%3};"
        : "+f"(c[0]), "+f"(c[1]), "+f"(c[2]), "+f"(c[3])
        : "r"(a0), "r"(a1), "r"(a2), "r"(a3), "r"(b0), "r"(b1));
}

// C = A[MxK] @ B[K x N, row stride ldB] (+bias)(+res)(relu). M%128==0, K%16==0.
// blockIdx.z selects (B,C) among up to 3 weight/output pairs (QKV fusion).
__global__ __launch_bounds__(256)
void gemm_tc(const float* __restrict__ A, const float* __restrict__ B,
             const float* __restrict__ bias, const float* __restrict__ res,
             float* __restrict__ C, int M, int N, int K, int ldB, int relu,
             const float* B1, const float* B2, float* C1, float* C2) {
    if (blockIdx.z == 1) { B = B1; C = C1; }
    else if (blockIdx.z == 2) { B = B2; C = C2; }

    __shared__ unsigned As[2][BK][BM + 4];
    __shared__ unsigned Bs[2][BK][BN + 4];

    int tid = threadIdx.x;
    int lane = tid & 31, wid = tid >> 5;
    int g = lane >> 2, tig = lane & 3;
    int wm = wid & 1, wn = wid >> 1;        // 2 x 4 warp grid, warp tile 64x32

    int m0 = blockIdx.x * BM, n0 = blockIdx.y * BN;

    int arow = tid >> 1, acol = (tid & 1) * 8;    // A: 128 rows x 16 cols
    int brow = tid >> 4, bcol = (tid & 15) * 8;   // B: 16 rows x 128 cols

    bool fastB = (n0 + BN <= ldB) && ((ldB & 3) == 0);

    const float* Aptr = A + (size_t)(m0 + arow) * K + acol;

    float c[4][4][4] = {};

    // prologue: tile 0 -> buf 0
    {
        float va[8], vb[8];
        *(float4*)&va[0] = *(const float4*)(Aptr);
        *(float4*)&va[4] = *(const float4*)(Aptr + 4);
        const float* Bp = B + (size_t)brow * ldB + n0 + bcol;
        if (fastB) {
            *(float4*)&vb[0] = *(const float4*)Bp;
            *(float4*)&vb[4] = *(const float4*)(Bp + 4);
        } else {
            #pragma unroll
            for (int j = 0; j < 8; j++)
                vb[j] = (n0 + bcol + j < N) ? Bp[j] : 0.0f;
        }
        #pragma unroll
        for (int j = 0; j < 8; j++) As[0][acol + j][arow] = f2tf(va[j]);
        #pragma unroll
        for (int j = 0; j < 8; j++) Bs[0][brow][bcol + j] = f2tf(vb[j]);
    }
    __syncthreads();

    int nk = K / BK;
    for (int it = 0; it < nk; it++) {
        int buf = it & 1;
        float va[8], vb[8];
        bool more = (it + 1 < nk);
        if (more) {
            int k0 = (it + 1) * BK;
            *(float4*)&va[0] = *(const float4*)(Aptr + k0);
            *(float4*)&va[4] = *(const float4*)(Aptr + k0 + 4);
            const float* Bp = B + (size_t)(k0 + brow) * ldB + n0 + bcol;
            if (fastB) {
                *(float4*)&vb[0] = *(const float4*)Bp;
                *(float4*)&vb[4] = *(const float4*)(Bp + 4);
            } else {
                #pragma unroll
                for (int j = 0; j < 8; j++)
                    vb[j] = (n0 + bcol + j < N) ? Bp[j] : 0.0f;
            }
        }

        #pragma unroll
        for (int ks = 0; ks < BK; ks += 8) {
            unsigned af[4][4], bf[4][2];
            #pragma unroll
            for (int mi = 0; mi < 4; mi++) {
                int m = wm * 64 + mi * 16 + g;
                af[mi][0] = As[buf][ks + tig][m];
                af[mi][1] = As[buf][ks + tig][m + 8];
                af[mi][2] = As[buf][ks + tig + 4][m];
                af[mi][3] = As[buf][ks + tig + 4][m + 8];
            }
            #pragma unroll
            for (int ni = 0; ni < 4; ni++) {
                int n = wn * 32 + ni * 8 + g;
                bf[ni][0] = Bs[buf][ks + tig][n];
                bf[ni][1] = Bs[buf][ks + tig + 4][n];
            }
            #pragma unroll
            for (int mi = 0; mi < 4; mi++)
                #pragma unroll
                for (int ni = 0; ni < 4; ni++)
                    mma_tf32(c[mi][ni], af[mi][0], af[mi][1], af[mi][2], af[mi][3],
                             bf[ni][0], bf[ni][1]);
        }

        if (more) {
            int nb = buf ^ 1;
            #pragma unroll
            for (int j = 0; j < 8; j++) As[nb][acol + j][arow] = f2tf(va[j]);
            #pragma unroll
            for (int j = 0; j < 8; j++) Bs[nb][brow][bcol + j] = f2tf(vb[j]);
        }
        __syncthreads();
    }

    // epilogue
    #pragma unroll
    for (int mi = 0; mi < 4; mi++) {
        int r0 = m0 + wm * 64 + mi * 16 + g;
        #pragma unroll
        for (int ni = 0; ni < 4; ni++) {
            int col = n0 + wn * 32 + ni * 8 + 2 * tig;
            #pragma unroll
            for (int rr = 0; rr < 2; rr++) {
                int r = r0 + rr * 8;
                #pragma unroll
                for (int cc = 0; cc < 2; cc++) {
                    int nn = col + cc;
                    if (nn < N) {
                        float v = c[mi][ni][rr * 2 + cc];
                        if (bias) v += bias[nn];
                        if (res)  v += res[(size_t)r * N + nn];
                        if (relu) v = fmaxf(v, 0.0f);
                        C[(size_t)r * N + nn] = v;
                    }
                }
            }
        }
    }
}

// ---------------- fused flash attention (fp32 SIMT, causal) -------------------
// grid (t_tile=16, bh=48), block 256, dynamic smem 4*64*FA_PAD floats
__global__ __launch_bounds__(256)
void flash_attn(const float* __restrict__ q, const float* __restrict__ k,
                const float* __restrict__ v, float* __restrict__ ao) {
    extern __shared__ float smf[];
    float* Qs = smf;                    // [64][FA_PAD]  Qs[d*FA_PAD + r] (transposed)
    float* Ks = smf + 64 * FA_PAD;      // Ks[d*FA_PAD + c]
    float* Vs = smf + 2 * 64 * FA_PAD;  // Vs[s*FA_PAD + j] (natural)
    float* Ps = smf + 3 * 64 * FA_PAD;  // Ps[s*FA_PAD + r] (transposed)

    int bh = blockIdx.y;
    int b = bh / Hn, h = bh % Hn;
    int tT = blockIdx.x;
    int t0 = tT * 64;

    int tid = threadIdx.x;
    int tx = tid & 15, ty = tid >> 4;
    int lr = tid >> 2;              // 0..63 (row for global loads)
    int lc0 = (tid & 3) * 16;       // 16 cols per loader thread

    // load Q tile (transposed, pre-scaled)
    {
        const float* qp = q + (size_t)(b * Tt + t0 + lr) * Dm + h * HS + lc0;
        #pragma unroll
        for (int u = 0; u < 4; u++) {
            float4 qv = *(const float4*)(qp + u * 4);
            Qs[(lc0 + u*4 + 0) * FA_PAD + lr] = qv.x * 0.125f;
            Qs[(lc0 + u*4 + 1) * FA_PAD + lr] = qv.y * 0.125f;
            Qs[(lc0 + u*4 + 2) * FA_PAD + lr] = qv.z * 0.125f;
            Qs[(lc0 + u*4 + 3) * FA_PAD + lr] = qv.w * 0.125f;
        }
    }

    float m[4], l[4], o[4][4];
    #pragma unroll
    for (int i = 0; i < 4; i++) {
        m[i] = -INFINITY; l[i] = 0.0f;
        #pragma unroll
        for (int j = 0; j < 4; j++) o[i][j] = 0.0f;
    }

    for (int st = 0; st <= tT; st++) {
        int s0 = st * 64;
        // load K (transposed) and V (natural)
        const float* kp = k + (size_t)(b * Tt + s0 + lr) * Dm + h * HS + lc0;
        const float* vp = v + (size_t)(b * Tt + s0 + lr) * Dm + h * HS + lc0;
        __syncthreads();            // protect Ks/Vs/Ps from previous iteration readers
        #pragma unroll
        for (int u = 0; u < 4; u++) {
            float4 kv = *(const float4*)(kp + u * 4);
            Ks[(lc0 + u*4 + 0) * FA_PAD + lr] = kv.x;
            Ks[(lc0 + u*4 + 1) * FA_PAD + lr] = kv.y;
            Ks[(lc0 + u*4 + 2) * FA_PAD + lr] = kv.z;
            Ks[(lc0 + u*4 + 3) * FA_PAD + lr] = kv.w;
            float4 vv = *(const float4*)(vp + u * 4);
            *(float4*)&Vs[lr * FA_PAD + lc0 + u * 4] = vv;
        }
        __syncthreads();

        // S = Q K^T  (64x64)
        float sacc[4][4] = {};
        #pragma unroll 8
        for (int d = 0; d < 64; d++) {
            float4 a = *(const float4*)&Qs[d * FA_PAD + ty * 4];
            float4 bb = *(const float4*)&Ks[d * FA_PAD + tx * 4];
            float ra[4] = {a.x, a.y, a.z, a.w};
            float rb[4] = {bb.x, bb.y, bb.z, bb.w};
            #pragma unroll
            for (int i = 0; i < 4; i++)
                #pragma unroll
                for (int j = 0; j < 4; j++)
                    sacc[i][j] = fmaf(ra[i], rb[j], sacc[i][j]);
        }

        if (st == tT) {
            #pragma unroll
            for (int i = 0; i < 4; i++) {
                int t = t0 + ty * 4 + i;
                #pragma unroll
                for (int j = 0; j < 4; j++)
                    if (s0 + tx * 4 + j > t) sacc[i][j] = -INFINITY;
            }
        }

        // online softmax update per row (row group = 16 lanes in half-warp)
        #pragma unroll
        for (int i = 0; i < 4; i++) {
            float mx = fmaxf(fmaxf(sacc[i][0], sacc[i][1]),
                             fmaxf(sacc[i][2], sacc[i][3]));
            #pragma unroll
            for (int off = 8; off; off >>= 1)
                mx = fmaxf(mx, __shfl_xor_sync(0xffffffffu, mx, off));
            float mnew = fmaxf(m[i], mx);
            float alpha = __expf(m[i] - mnew);
            float rs = 0.0f;
            #pragma unroll
            for (int j = 0; j < 4; j++) {
                float p = __expf(sacc[i][j] - mnew);
                sacc[i][j] = p;
                rs += p;
            }
            #pragma unroll
            for (int off = 8; off; off >>= 1)
                rs += __shfl_xor_sync(0xffffffffu, rs, off);
            l[i] = l[i] * alpha + rs;
            m[i] = mnew;
            #pragma unroll
            for (int j = 0; j < 4; j++) {
                o[i][j] *= alpha;
                Ps[(tx * 4 + j) * FA_PAD + ty * 4 + i] = sacc[i][j];
            }
        }
        __syncthreads();

        // O += P V
        #pragma unroll 8
        for (int s = 0; s < 64; s++) {
            float4 a = *(const float4*)&Ps[s * FA_PAD + ty * 4];
            float4 bb = *(const float4*)&Vs[s * FA_PAD + tx * 4];
            float ra[4] = {a.x, a.y, a.z, a.w};
            float rb[4] = {bb.x, bb.y, bb.z, bb.w};
            #pragma unroll
            for (int i = 0; i < 4; i++)
                #pragma unroll
                for (int j = 0; j < 4; j++)
                    o[i][j] = fmaf(ra[i], rb[j], o[i][j]);
        }
    }

    #pragma unroll
    for (int i = 0; i < 4; i++) {
        float inv = 1.0f / l[i];
        float4 r;
        r.x = o[i][0] * inv; r.y = o[i][1] * inv;
        r.z = o[i][2] * inv; r.w = o[i][3] * inv;
        *(float4*)(ao + (size_t)(b * Tt + t0 + ty * 4 + i) * Dm + h * HS + tx * 4) = r;
    }
}

// ---------------- per-row NLL ------------------------------------------------
__global__ void nll_kernel(const float* __restrict__ logits, const int* __restrict__ tgt,
                           float* __restrict__ nll) {
    int row = blockIdx.x;
    int tid = threadIdx.x;
    const float* lr = logits + (size_t)row * Vv;

    float m = -INFINITY, s = 0.0f;
    for (int i = tid; i < Vv; i += 256) {
        float x = lr[i];
        if (x > m) { s = s * expf(m - x) + 1.0f; m = x; }
        else       { s += expf(x - m); }
    }
    __shared__ float sm[256], ss[256];
    sm[tid] = m; ss[tid] = s;
    __syncthreads();
    for (int off = 128; off; off >>= 1) {
        if (tid < off) {
            float m2 = sm[tid + off], s2 = ss[tid + off];
            float mm = fmaxf(sm[tid], m2);
            ss[tid] = ss[tid] * expf(sm[tid] - mm) + s2 * expf(m2 - mm);
            sm[tid] = mm;
        }
        __syncthreads();
    }
    if (tid == 0) {
        float lse = sm[0] + logf(ss[0]);
        nll[row] = lse - lr[tgt[row]];
    }
}

__global__ void loss_reduce(const float* __restrict__ nll, float* __restrict__ out) {
    int tid = threadIdx.x;
    float s = 0.0f;
    for (int i = tid; i < MR; i += 256) s += nll[i];
    __shared__ float red[8];
    #pragma unroll
    for (int o = 16; o; o >>= 1) s += __shfl_xor_sync(0xffffffffu, s, o);
    if ((tid & 31) == 0) red[tid >> 5] = s;
    __syncthreads();
    if (tid == 0) {
        float tot = red[0]+red[1]+red[2]+red[3]+red[4]+red[5]+red[6]+red[7];
        out[0] = tot * (1.0f / MR);
    }
}

// ---------------- driver -----------------------------------------------------
extern "C" void kernel_launch(void* const* d_in, const int* in_sizes, int n_in,
                              void* d_out, int out_size) {
    const int*   idx   = (const int*)  d_in[0];
    const int*   tgt   = (const int*)  d_in[1];
    const float* tok   = (const float*)d_in[2];
    const float* pos   = (const float*)d_in[3];
    const float* ln1s  = (const float*)d_in[4];
    const float* ln1b  = (const float*)d_in[5];
    const float* Wq    = (const float*)d_in[6];
    const float* Wk    = (const float*)d_in[7];
    const float* Wv    = (const float*)d_in[8];
    const float* Wo    = (const float*)d_in[9];
    const float* bo    = (const float*)d_in[10];
    const float* ln2s  = (const float*)d_in[11];
    const float* ln2b  = (const float*)d_in[12];
    const float* W1    = (const float*)d_in[13];
    const float* b1    = (const float*)d_in[14];
    const float* W2    = (const float*)d_in[15];
    const float* b2    = (const float*)d_in[16];
    const float* lnfs  = (const float*)d_in[17];
    const float* lnfb  = (const float*)d_in[18];
    const float* lmW   = (const float*)d_in[19];
    const float* lmb   = (const float*)d_in[20];
    float* out = (float*)d_out;

    float *gx, *gh, *gq, *gk, *gv, *gao, *gmlp, *glmWp, *gnll;
    cudaGetSymbolAddress((void**)&gx,    g_x);
    cudaGetSymbolAddress((void**)&gh,    g_h);
    cudaGetSymbolAddress((void**)&gq,    g_q);
    cudaGetSymbolAddress((void**)&gk,    g_k);
    cudaGetSymbolAddress((void**)&gv,    g_v);
    cudaGetSymbolAddress((void**)&gao,   g_ao);
    cudaGetSymbolAddress((void**)&gmlp,  g_mlp);
    cudaGetSymbolAddress((void**)&glmWp, g_lmWp);
    cudaGetSymbolAddress((void**)&gnll,  g_nll);

    const int FA_SMEM = 4 * 64 * FA_PAD * sizeof(float);   // ~69.6 KB
    cudaFuncSetAttribute(flash_attn, cudaFuncAttributeMaxDynamicSharedMemorySize, FA_SMEM);

    pad_lmW<<<Dm, 256>>>(lmW, glmWp);
    embed_kernel<<<MR, 256>>>(idx, tok, pos, gx);

    dim3 gQKV(MR / BM, Dm / BN, 3);          // 32 x 6 x 3
    dim3 gDD (MR / BM, Dm / BN, 1);          // 32 x 6
    dim3 gF1 (MR / BM, FF / BN, 1);          // 32 x 24
    dim3 gFA(Tt / 64, Bb * Hn);              // 16 x 48

    for (int l = 0; l < Ln; l++) {
        const float* wq = Wq + (size_t)l * Dm * Dm;
        const float* wk = Wk + (size_t)l * Dm * Dm;
        const float* wv = Wv + (size_t)l * Dm * Dm;
        const float* wo = Wo + (size_t)l * Dm * Dm;
        const float* w1 = W1 + (size_t)l * Dm * FF;
        const float* w2 = W2 + (size_t)l * FF * Dm;

        ln_kernel<<<MR, 256>>>(gx, ln1s + l * Dm, ln1b + l * Dm, gh);
        gemm_tc<<<gQKV, 256>>>(gh, wq, nullptr, nullptr, gq, MR, Dm, Dm, Dm, 0,
                               wk, wv, gk, gv);

        flash_attn<<<gFA, 256, FA_SMEM>>>(gq, gk, gv, gao);

        gemm_tc<<<gDD, 256>>>(gao, wo, bo + l * Dm, gx, gx, MR, Dm, Dm, Dm, 0,
                              nullptr, nullptr, nullptr, nullptr);

        ln_kernel<<<MR, 256>>>(gx, ln2s + l * Dm, ln2b + l * Dm, gh);
        gemm_tc<<<gF1, 256>>>(gh, w1, b1 + (size_t)l * FF, nullptr, gmlp,
                              MR, FF, Dm, FF, 1, nullptr, nullptr, nullptr, nullptr);
        gemm_tc<<<gDD, 256>>>(gmlp, w2, b2 + l * Dm, gx, gx, MR, Dm, FF, Dm, 0,
                              nullptr, nullptr, nullptr, nullptr);
    }

    ln_kernel<<<MR, 256>>>(gx, lnfs, lnfb, gh);
    dim3 gV(MR / BM, NP / BN, 1);             // 32 x 393
    gemm_tc<<<gV, 256>>>(gh, glmWp, lmb, nullptr, out, MR, Vv, Dm, NP, 0,
                         nullptr, nullptr, nullptr, nullptr);

    nll_kernel<<<MR, 256>>>(out, tgt, gnll);
    loss_reduce<<<1, 256>>>(gnll, out + (size_t)out_size - 1);
}

// round 16
// speedup vs baseline: 2.5169x; 1.2092x over previous
#include <cuda_runtime.h>
#include <math.h>

#define Dm   768
#define Hn   12
#define HS   64
#define Ln   12
#define Tt   1024
#define Bb   4
#define Vv   50257
#define NP   50304           // lm_W padded stride (multiple of 128)
#define MR   4096            // B*T rows
#define FF   3072
#define EPSL 1e-5f

#define BM 128
#define BN 128
#define BK 16

// fragment-layout SMEM strides (in unsigned words)
#define A_KBLK 1028          // 8 mtiles * 128 + 4 pad
#define A_BUF  2056          // 2 kblks
#define B_NT   66            // 32 lanes * 2 + 2 pad
#define B_KBLK 1058          // 16 ntiles * 66 + 2 pad
#define B_BUF  2116          // 2 kblks

#define FA_PAD 68

// ---------------- scratch (static device globals; no runtime alloc) ----------
__device__ float g_x[MR * Dm];
__device__ float g_h[MR * Dm];
__device__ float g_q[MR * Dm];
__device__ float g_k[MR * Dm];
__device__ float g_v[MR * Dm];
__device__ float g_ao[MR * Dm];
__device__ float g_mlp[MR * FF];
__device__ float g_lmWp[(size_t)Dm * NP];    // padded lm_W, ~154 MB
__device__ float g_nll[MR];

// ---------------- embedding --------------------------------------------------
__global__ void embed_kernel(const int* __restrict__ idx,
                             const float* __restrict__ tok,
                             const float* __restrict__ pos,
                             float* __restrict__ x) {
    int row = blockIdx.x;
    int t = row & (Tt - 1);
    int tk = idx[row];
    const float* te = tok + (size_t)tk * Dm;
    const float* pe = pos + (size_t)t * Dm;
    float* xo = x + (size_t)row * Dm;
    for (int i = threadIdx.x; i < Dm; i += blockDim.x)
        xo[i] = te[i] + pe[i];
}

// ---------------- pad lm_W into stride-NP buffer ------------------------------
__global__ void pad_lmW(const float* __restrict__ w, float* __restrict__ wp) {
    int k = blockIdx.x;                                  // 0..767
    const float* src = w + (size_t)k * Vv;
    float* dst = wp + (size_t)k * NP;
    for (int j = threadIdx.x; j < NP; j += blockDim.x)
        dst[j] = (j < Vv) ? src[j] : 0.0f;
}

// ---------------- layernorm --------------------------------------------------
__global__ void ln_kernel(const float* __restrict__ x,
                          const float* __restrict__ gs,
                          const float* __restrict__ gb,
                          float* __restrict__ out) {
    int row = blockIdx.x;
    int tid = threadIdx.x;
    const float* xr = x + (size_t)row * Dm;
    float* orow = out + (size_t)row * Dm;

    float v0 = xr[tid], v1 = xr[tid + 256], v2 = xr[tid + 512];
    float s = v0 + v1 + v2;
    __shared__ float red[8];
    #pragma unroll
    for (int o = 16; o; o >>= 1) s += __shfl_xor_sync(0xffffffffu, s, o);
    if ((tid & 31) == 0) red[tid >> 5] = s;
    __syncthreads();
    float mean = (red[0]+red[1]+red[2]+red[3]+red[4]+red[5]+red[6]+red[7]) * (1.0f / Dm);
    __syncthreads();

    float d0 = v0 - mean, d1 = v1 - mean, d2 = v2 - mean;
    float sq = d0*d0 + d1*d1 + d2*d2;
    #pragma unroll
    for (int o = 16; o; o >>= 1) sq += __shfl_xor_sync(0xffffffffu, sq, o);
    if ((tid & 31) == 0) red[tid >> 5] = sq;
    __syncthreads();
    float var = (red[0]+red[1]+red[2]+red[3]+red[4]+red[5]+red[6]+red[7]) * (1.0f / Dm);
    float rs = rsqrtf(var + EPSL);

    orow[tid]       = d0 * rs * gs[tid]       + gb[tid];
    orow[tid + 256] = d1 * rs * gs[tid + 256] + gb[tid + 256];
    orow[tid + 512] = d2 * rs * gs[tid + 512] + gb[tid + 512];
}

// ---------------- tf32 tensor-core GEMM --------------------------------------
__device__ __forceinline__ unsigned f2tf(float f) {
    unsigned r;
    asm("cvt.rna.tf32.f32 %0, %1;" : "=r"(r) : "f"(f));
    return r;
}

__device__ __forceinline__ void mma_tf32(float* c, unsigned a0, unsigned a1,
                                         unsigned a2, unsigned a3,
                                         unsigned b0, unsigned b1) {
    asm volatile(
        "mma.sync.aligned.m16n8k8.row.col.f32.tf32.tf32.f32 "
        "{%0,%1,%2,%3}, {%4,%5,%6,%7}, {%8,%9}, {%0,%1,%2,%3};"
        : "+f"(c[0]), "+f"(c[1]), "+f"(c[2]), "+f"(c[3])
        : "r"(a0), "r"(a1), "r"(a2), "r"(a3), "r"(b0), "r"(b1));
}

// C = A[MxK] @ B[K x N, row stride ldB] (+bias)(+res)(relu). M%128==0, K%16==0.
// blockIdx.z selects (B,C) among up to 3 weight/output pairs (QKV fusion).
// SMEM holds tiles in mma-fragment order:
//   A: [kblk][mtile][lane][slot0..3] slots = {(g,tig),(g,tig+4),(g+8,tig),(g+8,tig+4)}
//   B: [kblk][ntile][lane][slot0..1] slots = {(tig,g),(tig+4,g)}
__global__ __launch_bounds__(256)
void gemm_tc(const float* __restrict__ A, const float* __restrict__ B,
             const float* __restrict__ bias, const float* __restrict__ res,
             float* __restrict__ C, int M, int N, int K, int ldB, int relu,
             const float* B1, const float* B2, float* C1, float* C2) {
    if (blockIdx.z == 1) { B = B1; C = C1; }
    else if (blockIdx.z == 2) { B = B2; C = C2; }

    __shared__ __align__(16) unsigned Asm[2 * A_BUF];
    __shared__ __align__(16) unsigned Bsm[2 * B_BUF];

    int tid = threadIdx.x;
    int lane = tid & 31, wid = tid >> 5;
    int g = lane >> 2, tig = lane & 3;
    int wm = wid & 1, wn = wid >> 1;        // 2 x 4 warp grid, warp tile 64x32

    int m0 = blockIdx.x * BM, n0 = blockIdx.y * BN;

    // ---- fill-side indices ----
    // A: thread loads 8 consecutive k from row arow; kblk = tid&1
    int arow = tid >> 1;
    int kb_a = tid & 1;
    int amtile = arow >> 4, amt = arow & 15;
    int ahalf = amt >> 3, ag = amt & 7;
    unsigned a_base = kb_a * A_KBLK + amtile * 128 + ahalf * 2;
    // B: thread loads 8 consecutive n from k-row krow
    int krow = tid >> 4;
    int kb_b = krow >> 3, bkk = krow & 7;
    int bhi = bkk >> 2, btig = bkk & 3;
    int bnt = tid & 15;
    unsigned b_base = kb_b * B_KBLK + bnt * B_NT + btig * 2 + bhi;

    int bcol = bnt * 8;
    bool fastB = (n0 + BN <= ldB) && ((ldB & 3) == 0);

    const float* Aptr = A + (size_t)(m0 + arow) * K + kb_a * 8;

    float c[4][4][4] = {};

    // prologue: tile 0 -> buf 0
    {
        float va[8], vb[8];
        *(float4*)&va[0] = *(const float4*)(Aptr);
        *(float4*)&va[4] = *(const float4*)(Aptr + 4);
        const float* Bp = B + (size_t)krow * ldB + n0 + bcol;
        if (fastB) {
            *(float4*)&vb[0] = *(const float4*)Bp;
            *(float4*)&vb[4] = *(const float4*)(Bp + 4);
        } else {
            #pragma unroll
            for (int j = 0; j < 8; j++)
                vb[j] = (n0 + bcol + j < N) ? Bp[j] : 0.0f;
        }
        #pragma unroll
        for (int t = 0; t < 4; t++)
            *(uint2*)&Asm[a_base + (ag * 4 + t) * 4] =
                make_uint2(f2tf(va[t]), f2tf(va[t + 4]));
        #pragma unroll
        for (int j = 0; j < 8; j++)
            Bsm[b_base + j * 8] = f2tf(vb[j]);
    }
    __syncthreads();

    int nk = K / BK;
    for (int it = 0; it < nk; it++) {
        int buf = it & 1;
        float va[8], vb[8];
        bool more = (it + 1 < nk);
        if (more) {
            int k0 = (it + 1) * BK;
            *(float4*)&va[0] = *(const float4*)(Aptr + k0);
            *(float4*)&va[4] = *(const float4*)(Aptr + k0 + 4);
            const float* Bp = B + (size_t)(k0 + krow) * ldB + n0 + bcol;
            if (fastB) {
                *(float4*)&vb[0] = *(const float4*)Bp;
                *(float4*)&vb[4] = *(const float4*)(Bp + 4);
            } else {
                #pragma unroll
                for (int j = 0; j < 8; j++)
                    vb[j] = (n0 + bcol + j < N) ? Bp[j] : 0.0f;
            }
        }

        unsigned abuf = buf * A_BUF;
        unsigned bbuf = buf * B_BUF;
        #pragma unroll
        for (int ks8 = 0; ks8 < 2; ks8++) {
            uint4 av[4];
            uint2 bv[4];
            #pragma unroll
            for (int mi = 0; mi < 4; mi++)
                av[mi] = *(const uint4*)&Asm[abuf + ks8 * A_KBLK +
                                             (wm * 4 + mi) * 128 + lane * 4];
            #pragma unroll
            for (int ni = 0; ni < 4; ni++)
                bv[ni] = *(const uint2*)&Bsm[bbuf + ks8 * B_KBLK +
                                             (wn * 4 + ni) * B_NT + lane * 2];
            #pragma unroll
            for (int mi = 0; mi < 4; mi++)
                #pragma unroll
                for (int ni = 0; ni < 4; ni++)
                    mma_tf32(c[mi][ni], av[mi].x, av[mi].z, av[mi].y, av[mi].w,
                             bv[ni].x, bv[ni].y);
        }

        if (more) {
            unsigned nb = (buf ^ 1);
            unsigned an = nb * A_BUF, bn = nb * B_BUF;
            #pragma unroll
            for (int t = 0; t < 4; t++)
                *(uint2*)&Asm[an + a_base + (ag * 4 + t) * 4] =
                    make_uint2(f2tf(va[t]), f2tf(va[t + 4]));
            #pragma unroll
            for (int j = 0; j < 8; j++)
                Bsm[bn + b_base + j * 8] = f2tf(vb[j]);
        }
        __syncthreads();
    }

    // epilogue: float2 stores only when every row offset stays 8B-aligned (N even)
    bool evenN = ((N & 1) == 0);
    #pragma unroll
    for (int mi = 0; mi < 4; mi++) {
        int r0 = m0 + wm * 64 + mi * 16 + g;
        #pragma unroll
        for (int ni = 0; ni < 4; ni++) {
            int col = n0 + wn * 32 + ni * 8 + 2 * tig;
            #pragma unroll
            for (int rr = 0; rr < 2; rr++) {
                int r = r0 + rr * 8;
                float v0 = c[mi][ni][rr * 2 + 0];
                float v1 = c[mi][ni][rr * 2 + 1];
                if (evenN && col + 1 < N) {
                    if (bias) { v0 += bias[col]; v1 += bias[col + 1]; }
                    if (res) {
                        float2 rv = *(const float2*)&res[(size_t)r * N + col];
                        v0 += rv.x; v1 += rv.y;
                    }
                    if (relu) { v0 = fmaxf(v0, 0.0f); v1 = fmaxf(v1, 0.0f); }
                    float2 ov; ov.x = v0; ov.y = v1;
                    *(float2*)&C[(size_t)r * N + col] = ov;
                } else {
                    #pragma unroll
                    for (int cc = 0; cc < 2; cc++) {
                        int nn = col + cc;
                        if (nn < N) {
                            float v = (cc == 0) ? v0 : v1;
                            if (bias) v += bias[nn];
                            if (res)  v += res[(size_t)r * N + nn];
                            if (relu) v = fmaxf(v, 0.0f);
                            C[(size_t)r * N + nn] = v;
                        }
                    }
                }
            }
        }
    }
}

// ---------------- fused flash attention (fp32 SIMT, causal) -------------------
// grid (t_tile=16, bh=48), block 256, dynamic smem 4*64*FA_PAD floats
__global__ __launch_bounds__(256)
void flash_attn(const float* __restrict__ q, const float* __restrict__ k,
                const float* __restrict__ v, float* __restrict__ ao) {
    extern __shared__ float smf[];
    float* Qs = smf;                    // [64][FA_PAD]  Qs[d*FA_PAD + r] (transposed)
    float* Ks = smf + 64 * FA_PAD;      // Ks[d*FA_PAD + c]
    float* Vs = smf + 2 * 64 * FA_PAD;  // Vs[s*FA_PAD + j] (natural)
    float* Ps = smf + 3 * 64 * FA_PAD;  // Ps[s*FA_PAD + r] (transposed)

    int bh = blockIdx.y;
    int b = bh / Hn, h = bh % Hn;
    int tT = blockIdx.x;
    int t0 = tT * 64;

    int tid = threadIdx.x;
    int tx = tid & 15, ty = tid >> 4;
    int lr = tid >> 2;              // 0..63 (row for global loads)
    int lc0 = (tid & 3) * 16;       // 16 cols per loader thread

    // load Q tile (transposed, pre-scaled)
    {
        const float* qp = q + (size_t)(b * Tt + t0 + lr) * Dm + h * HS + lc0;
        #pragma unroll
        for (int u = 0; u < 4; u++) {
            float4 qv = *(const float4*)(qp + u * 4);
            Qs[(lc0 + u*4 + 0) * FA_PAD + lr] = qv.x * 0.125f;
            Qs[(lc0 + u*4 + 1) * FA_PAD + lr] = qv.y * 0.125f;
            Qs[(lc0 + u*4 + 2) * FA_PAD + lr] = qv.z * 0.125f;
            Qs[(lc0 + u*4 + 3) * FA_PAD + lr] = qv.w * 0.125f;
        }
    }

    float m[4], l[4], o[4][4];
    #pragma unroll
    for (int i = 0; i < 4; i++) {
        m[i] = -INFINITY; l[i] = 0.0f;
        #pragma unroll
        for (int j = 0; j < 4; j++) o[i][j] = 0.0f;
    }

    for (int st = 0; st <= tT; st++) {
        int s0 = st * 64;
        const float* kp = k + (size_t)(b * Tt + s0 + lr) * Dm + h * HS + lc0;
        const float* vp = v + (size_t)(b * Tt + s0 + lr) * Dm + h * HS + lc0;
        __syncthreads();
        #pragma unroll
        for (int u = 0; u < 4; u++) {
            float4 kv = *(const float4*)(kp + u * 4);
            Ks[(lc0 + u*4 + 0) * FA_PAD + lr] = kv.x;
            Ks[(lc0 + u*4 + 1) * FA_PAD + lr] = kv.y;
            Ks[(lc0 + u*4 + 2) * FA_PAD + lr] = kv.z;
            Ks[(lc0 + u*4 + 3) * FA_PAD + lr] = kv.w;
            float4 vv = *(const float4*)(vp + u * 4);
            *(float4*)&Vs[lr * FA_PAD + lc0 + u * 4] = vv;
        }
        __syncthreads();

        // S = Q K^T  (64x64)
        float sacc[4][4] = {};
        #pragma unroll 8
        for (int d = 0; d < 64; d++) {
            float4 a = *(const float4*)&Qs[d * FA_PAD + ty * 4];
            float4 bb = *(const float4*)&Ks[d * FA_PAD + tx * 4];
            float ra[4] = {a.x, a.y, a.z, a.w};
            float rb[4] = {bb.x, bb.y, bb.z, bb.w};
            #pragma unroll
            for (int i = 0; i < 4; i++)
                #pragma unroll
                for (int j = 0; j < 4; j++)
                    sacc[i][j] = fmaf(ra[i], rb[j], sacc[i][j]);
        }

        if (st == tT) {
            #pragma unroll
            for (int i = 0; i < 4; i++) {
                int t = t0 + ty * 4 + i;
                #pragma unroll
                for (int j = 0; j < 4; j++)
                    if (s0 + tx * 4 + j > t) sacc[i][j] = -INFINITY;
            }
        }

        // online softmax update per row (row group = 16 lanes in half-warp)
        #pragma unroll
        for (int i = 0; i < 4; i++) {
            float mx = fmaxf(fmaxf(sacc[i][0], sacc[i][1]),
                             fmaxf(sacc[i][2], sacc[i][3]));
            #pragma unroll
            for (int off = 8; off; off >>= 1)
                mx = fmaxf(mx, __shfl_xor_sync(0xffffffffu, mx, off));
            float mnew = fmaxf(m[i], mx);
            float alpha = __expf(m[i] - mnew);
            float rs = 0.0f;
            #pragma unroll
            for (int j = 0; j < 4; j++) {
                float p = __expf(sacc[i][j] - mnew);
                sacc[i][j] = p;
                rs += p;
            }
            #pragma unroll
            for (int off = 8; off; off >>= 1)
                rs += __shfl_xor_sync(0xffffffffu, rs, off);
            l[i] = l[i] * alpha + rs;
            m[i] = mnew;
            #pragma unroll
            for (int j = 0; j < 4; j++) {
                o[i][j] *= alpha;
                Ps[(tx * 4 + j) * FA_PAD + ty * 4 + i] = sacc[i][j];
            }
        }
        __syncthreads();

        // O += P V
        #pragma unroll 8
        for (int s = 0; s < 64; s++) {
            float4 a = *(const float4*)&Ps[s * FA_PAD + ty * 4];
            float4 bb = *(const float4*)&Vs[s * FA_PAD + tx * 4];
            float ra[4] = {a.x, a.y, a.z, a.w};
            float rb[4] = {bb.x, bb.y, bb.z, bb.w};
            #pragma unroll
            for (int i = 0; i < 4; i++)
                #pragma unroll
                for (int j = 0; j < 4; j++)
                    o[i][j] = fmaf(ra[i], rb[j], o[i][j]);
        }
    }

    #pragma unroll
    for (int i = 0; i < 4; i++) {
        float inv = 1.0f / l[i];
        float4 r;
        r.x = o[i][0] * inv; r.y = o[i][1] * inv;
        r.z = o[i][2] * inv; r.w = o[i][3] * inv;
        *(float4*)(ao + (size_t)(b * Tt + t0 + ty * 4 + i) * Dm + h * HS + tx * 4) = r;
    }
}

// ---------------- per-row NLL ------------------------------------------------
__global__ void nll_kernel(const float* __restrict__ logits, const int* __restrict__ tgt,
                           float* __restrict__ nll) {
    int row = blockIdx.x;
    int tid = threadIdx.x;
    const float* lr = logits + (size_t)row * Vv;

    float m = -INFINITY, s = 0.0f;
    for (int i = tid; i < Vv; i += 256) {
        float x = lr[i];
        if (x > m) { s = s * expf(m - x) + 1.0f; m = x; }
        else       { s += expf(x - m); }
    }
    __shared__ float sm[256], ss[256];
    sm[tid] = m; ss[tid] = s;
    __syncthreads();
    for (int off = 128; off; off >>= 1) {
        if (tid < off) {
            float m2 = sm[tid + off], s2 = ss[tid + off];
            float mm = fmaxf(sm[tid], m2);
            ss[tid] = ss[tid] * expf(sm[tid] - mm) + s2 * expf(m2 - mm);
            sm[tid] = mm;
        }
        __syncthreads();
    }
    if (tid == 0) {
        float lse = sm[0] + logf(ss[0]);
        nll[row] = lse - lr[tgt[row]];
    }
}

__global__ void loss_reduce(const float* __restrict__ nll, float* __restrict__ out) {
    int tid = threadIdx.x;
    float s = 0.0f;
    for (int i = tid; i < MR; i += 256) s += nll[i];
    __shared__ float red[8];
    #pragma unroll
    for (int o = 16; o; o >>= 1) s += __shfl_xor_sync(0xffffffffu, s, o);
    if ((tid & 31) == 0) red[tid >> 5] = s;
    __syncthreads();
    if (tid == 0) {
        float tot = red[0]+red[1]+red[2]+red[3]+red[4]+red[5]+red[6]+red[7];
        out[0] = tot * (1.0f / MR);
    }
}

// ---------------- driver -----------------------------------------------------
extern "C" void kernel_launch(void* const* d_in, const int* in_sizes, int n_in,
                              void* d_out, int out_size) {
    const int*   idx   = (const int*)  d_in[0];
    const int*   tgt   = (const int*)  d_in[1];
    const float* tok   = (const float*)d_in[2];
    const float* pos   = (const float*)d_in[3];
    const float* ln1s  = (const float*)d_in[4];
    const float* ln1b  = (const float*)d_in[5];
    const float* Wq    = (const float*)d_in[6];
    const float* Wk    = (const float*)d_in[7];
    const float* Wv    = (const float*)d_in[8];
    const float* Wo    = (const float*)d_in[9];
    const float* bo    = (const float*)d_in[10];
    const float* ln2s  = (const float*)d_in[11];
    const float* ln2b  = (const float*)d_in[12];
    const float* W1    = (const float*)d_in[13];
    const float* b1    = (const float*)d_in[14];
    const float* W2    = (const float*)d_in[15];
    const float* b2    = (const float*)d_in[16];
    const float* lnfs  = (const float*)d_in[17];
    const float* lnfb  = (const float*)d_in[18];
    const float* lmW   = (const float*)d_in[19];
    const float* lmb   = (const float*)d_in[20];
    float* out = (float*)d_out;

    float *gx, *gh, *gq, *gk, *gv, *gao, *gmlp, *glmWp, *gnll;
    cudaGetSymbolAddress((void**)&gx,    g_x);
    cudaGetSymbolAddress((void**)&gh,    g_h);
    cudaGetSymbolAddress((void**)&gq,    g_q);
    cudaGetSymbolAddress((void**)&gk,    g_k);
    cudaGetSymbolAddress((void**)&gv,    g_v);
    cudaGetSymbolAddress((void**)&gao,   g_ao);
    cudaGetSymbolAddress((void**)&gmlp,  g_mlp);
    cudaGetSymbolAddress((void**)&glmWp, g_lmWp);
    cudaGetSymbolAddress((void**)&gnll,  g_nll);

    const int FA_SMEM = 4 * 64 * FA_PAD * sizeof(float);   // ~69.6 KB
    cudaFuncSetAttribute(flash_attn, cudaFuncAttributeMaxDynamicSharedMemorySize, FA_SMEM);

    pad_lmW<<<Dm, 256>>>(lmW, glmWp);
    embed_kernel<<<MR, 256>>>(idx, tok, pos, gx);

    dim3 gQKV(MR / BM, Dm / BN, 3);          // 32 x 6 x 3
    dim3 gDD (MR / BM, Dm / BN, 1);          // 32 x 6
    dim3 gF1 (MR / BM, FF / BN, 1);          // 32 x 24
    dim3 gFA(Tt / 64, Bb * Hn);              // 16 x 48

    for (int l = 0; l < Ln; l++) {
        const float* wq = Wq + (size_t)l * Dm * Dm;
        const float* wk = Wk + (size_t)l * Dm * Dm;
        const float* wv = Wv + (size_t)l * Dm * Dm;
        const float* wo = Wo + (size_t)l * Dm * Dm;
        const float* w1 = W1 + (size_t)l * Dm * FF;
        const float* w2 = W2 + (size_t)l * FF * Dm;

        ln_kernel<<<MR, 256>>>(gx, ln1s + l * Dm, ln1b + l * Dm, gh);
        gemm_tc<<<gQKV, 256>>>(gh, wq, nullptr, nullptr, gq, MR, Dm, Dm, Dm, 0,
                               wk, wv, gk, gv);

        flash_attn<<<gFA, 256, FA_SMEM>>>(gq, gk, gv, gao);

        gemm_tc<<<gDD, 256>>>(gao, wo, bo + l * Dm, gx, gx, MR, Dm, Dm, Dm, 0,
                              nullptr, nullptr, nullptr, nullptr);

        ln_kernel<<<MR, 256>>>(gx, ln2s + l * Dm, ln2b + l * Dm, gh);
        gemm_tc<<<gF1, 256>>>(gh, w1, b1 + (size_t)l * FF, nullptr, gmlp,
                              MR, FF, Dm, FF, 1, nullptr, nullptr, nullptr, nullptr);
        gemm_tc<<<gDD, 256>>>(gmlp, w2, b2 + l * Dm, gx, gx, MR, Dm, FF, Dm, 0,
                              nullptr, nullptr, nullptr, nullptr);
    }

    ln_kernel<<<MR, 256>>>(gx, lnfs, lnfb, gh);
    dim3 gV(MR / BM, NP / BN, 1);             // 32 x 393
    gemm_tc<<<gV, 256>>>(gh, glmWp, lmb, nullptr, out, MR, Vv, Dm, NP, 0,
                         nullptr, nullptr, nullptr, nullptr);

    nll_kernel<<<MR, 256>>>(out, tgt, gnll);
    loss_reduce<<<1, 256>>>(gnll, out + (size_t)out_size - 1);
}